// round 1
// baseline (speedup 1.0000x reference)
#include <cuda_runtime.h>
#include <math.h>

// Problem constants (fixed shapes)
#define B_    2
#define N_    2048
#define DIM_  2048
#define H_    16
#define HD_   128
#define INNER (H_*HD_)      // 2048
#define QKV_E (3*INNER)     // 6144
#define EPS_  1e-5f

// ---------------------------------------------------------------------------
// Scratch (no cudaMalloc allowed -> __device__ globals)
// ---------------------------------------------------------------------------
__device__ float g_qkv[(size_t)B_*N_*QKV_E];   // [b*N+n][e]            ~100 MB
__device__ float g_q  [(size_t)B_*H_*N_*HD_];  // [b][h][n][d]           32 MB
__device__ float g_k  [(size_t)B_*H_*N_*HD_];
__device__ float g_v  [(size_t)B_*H_*N_*HD_];
__device__ float g_att[(size_t)B_*N_*INNER];   // [b][n][h*HD+d]         32 MB

// ---------------------------------------------------------------------------
// SGEMM (NT): C[M][Nc] = A[M][K] * B[Nc][K]^T.  Both operands K-contiguous.
// BM=BN=128, BK=16, 256 threads, 8x8 micro tile.
// ---------------------------------------------------------------------------
__global__ __launch_bounds__(256, 2)
void sgemm_nt(const float* __restrict__ A, const float* __restrict__ Bw,
              float* __restrict__ C, int M, int Nc, int K)
{
    __shared__ float As[16][128];
    __shared__ float Bs[16][128];

    const int tid = threadIdx.x;
    const int tx  = tid & 15;
    const int ty  = tid >> 4;
    const int bm  = blockIdx.y * 128;
    const int bn  = blockIdx.x * 128;

    const int lrow = tid >> 2;        // 0..63
    const int lk4  = (tid & 3) * 4;   // 0,4,8,12

    float acc[8][8];
#pragma unroll
    for (int i = 0; i < 8; i++)
#pragma unroll
        for (int j = 0; j < 8; j++) acc[i][j] = 0.f;

    for (int k0 = 0; k0 < K; k0 += 16) {
#pragma unroll
        for (int r = 0; r < 128; r += 64) {
            float4 a = *(const float4*)(A + (size_t)(bm + lrow + r) * K + k0 + lk4);
            As[lk4 + 0][lrow + r] = a.x;
            As[lk4 + 1][lrow + r] = a.y;
            As[lk4 + 2][lrow + r] = a.z;
            As[lk4 + 3][lrow + r] = a.w;
        }
#pragma unroll
        for (int r = 0; r < 128; r += 64) {
            float4 b = *(const float4*)(Bw + (size_t)(bn + lrow + r) * K + k0 + lk4);
            Bs[lk4 + 0][lrow + r] = b.x;
            Bs[lk4 + 1][lrow + r] = b.y;
            Bs[lk4 + 2][lrow + r] = b.z;
            Bs[lk4 + 3][lrow + r] = b.w;
        }
        __syncthreads();

#pragma unroll
        for (int kk = 0; kk < 16; kk++) {
            float a[8], b[8];
            *(float4*)&a[0] = *(float4*)&As[kk][ty * 8];
            *(float4*)&a[4] = *(float4*)&As[kk][ty * 8 + 4];
            *(float4*)&b[0] = *(float4*)&Bs[kk][tx * 8];
            *(float4*)&b[4] = *(float4*)&Bs[kk][tx * 8 + 4];
#pragma unroll
            for (int i = 0; i < 8; i++)
#pragma unroll
                for (int j = 0; j < 8; j++)
                    acc[i][j] = fmaf(a[i], b[j], acc[i][j]);
        }
        __syncthreads();
    }

#pragma unroll
    for (int i = 0; i < 8; i++) {
        const int row = bm + ty * 8 + i;
        float4* cp = (float4*)(C + (size_t)row * Nc + bn + tx * 8);
        cp[0] = make_float4(acc[i][0], acc[i][1], acc[i][2], acc[i][3]);
        cp[1] = make_float4(acc[i][4], acc[i][5], acc[i][6], acc[i][7]);
    }
}

// ---------------------------------------------------------------------------
// RMSNorm + RoPE + layout transform.
// grid (N, H, B), block 128.  One block handles one (b,h,n) 128-vector of q,k,v.
// ---------------------------------------------------------------------------
__global__ __launch_bounds__(128)
void qk_norm_rope(const float* __restrict__ qkv,
                  const float* __restrict__ qg, const float* __restrict__ kg,
                  const float* __restrict__ freqs,
                  float* __restrict__ Qo, float* __restrict__ Ko, float* __restrict__ Vo)
{
    const int n = blockIdx.x, h = blockIdx.y, b = blockIdx.z;
    const int d = threadIdx.x;   // 0..127

    const float* base = qkv + (size_t)(b * N_ + n) * QKV_E + h * HD_ + d;
    float qv = base[0];
    float kv = base[INNER];
    float vv = base[2 * INNER];

    // sum of squares over the 128 lanes (4 warps)
    __shared__ float red[2][4];
    float sq = qv * qv, sk = kv * kv;
#pragma unroll
    for (int off = 16; off; off >>= 1) {
        sq += __shfl_xor_sync(0xffffffffu, sq, off);
        sk += __shfl_xor_sync(0xffffffffu, sk, off);
    }
    const int warp = d >> 5, lane = d & 31;
    if (lane == 0) { red[0][warp] = sq; red[1][warp] = sk; }
    __syncthreads();
    sq = red[0][0] + red[0][1] + red[0][2] + red[0][3];
    sk = red[1][0] + red[1][1] + red[1][2] + red[1][3];

    const float rq = rsqrtf(sq * (1.0f / HD_) + EPS_);
    const float rk = rsqrtf(sk * (1.0f / HD_) + EPS_);
    qv = qv * rq * qg[d];
    kv = kv * rk * kg[d];

    // RoPE: pairs (2i, 2i+1)
    const float* f = freqs + ((size_t)(b * N_ + n) * (HD_ / 2) + (d >> 1)) * 2;
    const float c = f[0], s = f[1];
    const float qp = __shfl_xor_sync(0xffffffffu, qv, 1);
    const float kp = __shfl_xor_sync(0xffffffffu, kv, 1);
    float qo, ko;
    if ((d & 1) == 0) { qo = qv * c - qp * s;  ko = kv * c - kp * s; }
    else              { qo = qp * s + qv * c;  ko = kp * s + kv * c; }

    const size_t oidx = (((size_t)(b * H_ + h) * N_ + n) * HD_ + d);
    Qo[oidx] = qo;
    Ko[oidx] = ko;
    Vo[oidx] = vv;
}

// ---------------------------------------------------------------------------
// Flash attention, fp32, online softmax.
// grid (N/32, H, B), block 256 (16x16 thread tile over a 32x32 score tile;
// each thread owns 2 rows x 2 cols of S and 2 rows x 8 cols of O).
// ---------------------------------------------------------------------------
__global__ __launch_bounds__(256, 2)
void flash_attn(const float* __restrict__ Q, const float* __restrict__ K,
                const float* __restrict__ V, float* __restrict__ Oo)
{
    __shared__ float Qs [32][HD_ + 4];
    __shared__ float KVs[32][HD_ + 4];
    __shared__ float Ps [32][33];

    const int tid = threadIdx.x;
    const int tx  = tid & 15;
    const int ty  = tid >> 4;
    const int qt  = blockIdx.x;
    const int h   = blockIdx.y;
    const int b   = blockIdx.z;
    const size_t bh = ((size_t)b * H_ + h) * (size_t)N_ * HD_;

    // load Q tile (32 x 128)
    for (int i = tid * 4; i < 32 * HD_; i += 256 * 4) {
        const int r = i >> 7, c = i & 127;
        *(float4*)&Qs[r][c] = *(const float4*)(Q + bh + (size_t)(qt * 32 + r) * HD_ + c);
    }

    const int r0 = ty * 2;
    const int c0 = tx * 2;
    const float scale = 0.08838834764831845f;  // 1/sqrt(128)

    float m[2] = { -INFINITY, -INFINITY };
    float l[2] = { 0.f, 0.f };
    float o[2][8];
#pragma unroll
    for (int i = 0; i < 2; i++)
#pragma unroll
        for (int j = 0; j < 8; j++) o[i][j] = 0.f;

    for (int kt = 0; kt < N_ / 32; kt++) {
        // ---- load K tile ----
        for (int i = tid * 4; i < 32 * HD_; i += 256 * 4) {
            const int r = i >> 7, c = i & 127;
            *(float4*)&KVs[r][c] = *(const float4*)(K + bh + (size_t)(kt * 32 + r) * HD_ + c);
        }
        __syncthreads();

        // ---- S = Q K^T (each thread: 2x2) ----
        float s[2][2] = { {0.f, 0.f}, {0.f, 0.f} };
#pragma unroll
        for (int dd = 0; dd < HD_; dd += 4) {
            float4 a0 = *(float4*)&Qs[r0][dd];
            float4 a1 = *(float4*)&Qs[r0 + 1][dd];
            float4 b0 = *(float4*)&KVs[c0][dd];
            float4 b1 = *(float4*)&KVs[c0 + 1][dd];
            s[0][0] += a0.x*b0.x + a0.y*b0.y + a0.z*b0.z + a0.w*b0.w;
            s[0][1] += a0.x*b1.x + a0.y*b1.y + a0.z*b1.z + a0.w*b1.w;
            s[1][0] += a1.x*b0.x + a1.y*b0.y + a1.z*b0.z + a1.w*b0.w;
            s[1][1] += a1.x*b1.x + a1.y*b1.y + a1.z*b1.z + a1.w*b1.w;
        }

        // ---- online softmax (row groups of 16 lanes, xor-shuffle) ----
#pragma unroll
        for (int i = 0; i < 2; i++) {
            float s0 = s[i][0] * scale;
            float s1 = s[i][1] * scale;
            float rm = fmaxf(s0, s1);
#pragma unroll
            for (int off = 8; off; off >>= 1)
                rm = fmaxf(rm, __shfl_xor_sync(0xffffffffu, rm, off));
            const float mn = fmaxf(m[i], rm);
            const float alpha = __expf(m[i] - mn);
            const float p0 = __expf(s0 - mn);
            const float p1 = __expf(s1 - mn);
            float rs = p0 + p1;
#pragma unroll
            for (int off = 8; off; off >>= 1)
                rs += __shfl_xor_sync(0xffffffffu, rs, off);
            l[i] = l[i] * alpha + rs;
            m[i] = mn;
#pragma unroll
            for (int j = 0; j < 8; j++) o[i][j] *= alpha;
            Ps[r0 + i][c0]     = p0;
            Ps[r0 + i][c0 + 1] = p1;
        }
        __syncthreads();   // Ps complete; K reads done -> safe to overwrite with V

        // ---- load V tile into the same buffer ----
        for (int i = tid * 4; i < 32 * HD_; i += 256 * 4) {
            const int r = i >> 7, c = i & 127;
            *(float4*)&KVs[r][c] = *(const float4*)(V + bh + (size_t)(kt * 32 + r) * HD_ + c);
        }
        __syncthreads();

        // ---- O += P V  (each thread: 2 rows x 8 cols) ----
#pragma unroll 4
        for (int kk = 0; kk < 32; kk++) {
            const float p0 = Ps[r0][kk];
            const float p1 = Ps[r0 + 1][kk];
            float4 v0 = *(float4*)&KVs[kk][tx * 8];
            float4 v1 = *(float4*)&KVs[kk][tx * 8 + 4];
            o[0][0] = fmaf(p0, v0.x, o[0][0]);  o[0][1] = fmaf(p0, v0.y, o[0][1]);
            o[0][2] = fmaf(p0, v0.z, o[0][2]);  o[0][3] = fmaf(p0, v0.w, o[0][3]);
            o[0][4] = fmaf(p0, v1.x, o[0][4]);  o[0][5] = fmaf(p0, v1.y, o[0][5]);
            o[0][6] = fmaf(p0, v1.z, o[0][6]);  o[0][7] = fmaf(p0, v1.w, o[0][7]);
            o[1][0] = fmaf(p1, v0.x, o[1][0]);  o[1][1] = fmaf(p1, v0.y, o[1][1]);
            o[1][2] = fmaf(p1, v0.z, o[1][2]);  o[1][3] = fmaf(p1, v0.w, o[1][3]);
            o[1][4] = fmaf(p1, v1.x, o[1][4]);  o[1][5] = fmaf(p1, v1.y, o[1][5]);
            o[1][6] = fmaf(p1, v1.z, o[1][6]);  o[1][7] = fmaf(p1, v1.w, o[1][7]);
        }
        __syncthreads();   // all V/P reads done before next K load
    }

    // ---- normalize + write: attnout[b][n][h*HD + dc] ----
#pragma unroll
    for (int i = 0; i < 2; i++) {
        const float inv = 1.0f / l[i];
        const int n = qt * 32 + r0 + i;
        float* dst = Oo + ((size_t)(b * N_ + n)) * INNER + h * HD_ + tx * 8;
        *(float4*)(dst)     = make_float4(o[i][0]*inv, o[i][1]*inv, o[i][2]*inv, o[i][3]*inv);
        *(float4*)(dst + 4) = make_float4(o[i][4]*inv, o[i][5]*inv, o[i][6]*inv, o[i][7]*inv);
    }
}

// ---------------------------------------------------------------------------
// Launch
// ---------------------------------------------------------------------------
extern "C" void kernel_launch(void* const* d_in, const int* in_sizes, int n_in,
                              void* d_out, int out_size)
{
    const float* x     = (const float*)d_in[0];   // [2,2048,2048]
    const float* Wqkv  = (const float*)d_in[1];   // [6144,2048]
    const float* qg    = (const float*)d_in[2];   // [128]
    const float* kg    = (const float*)d_in[3];   // [128]
    const float* Wout  = (const float*)d_in[4];   // [2048,2048]
    const float* freqs = (const float*)d_in[5];   // [2,2048,64,2]
    float* out = (float*)d_out;                   // [2,2048,2048]

    void *p_qkv, *p_q, *p_k, *p_v, *p_att;
    cudaGetSymbolAddress(&p_qkv, g_qkv);
    cudaGetSymbolAddress(&p_q,   g_q);
    cudaGetSymbolAddress(&p_k,   g_k);
    cudaGetSymbolAddress(&p_v,   g_v);
    cudaGetSymbolAddress(&p_att, g_att);
    float* qkv = (float*)p_qkv;
    float* q   = (float*)p_q;
    float* k   = (float*)p_k;
    float* v   = (float*)p_v;
    float* att = (float*)p_att;

    // 1) QKV projection: [4096,2048] x [6144,2048]^T -> [4096,6144]
    sgemm_nt<<<dim3(QKV_E / 128, (B_ * N_) / 128), 256>>>(
        x, Wqkv, qkv, B_ * N_, QKV_E, DIM_);

    // 2) RMSNorm + RoPE + relayout
    qk_norm_rope<<<dim3(N_, H_, B_), 128>>>(qkv, qg, kg, freqs, q, k, v);

    // 3) attention
    flash_attn<<<dim3(N_ / 32, H_, B_), 256>>>(q, k, v, att);

    // 4) output projection: [4096,2048] x [2048,2048]^T -> [4096,2048]
    sgemm_nt<<<dim3(DIM_ / 128, (B_ * N_) / 128), 256>>>(
        att, Wout, out, B_ * N_, DIM_, INNER);
}

// round 5
// speedup vs baseline: 2.8593x; 2.8593x over previous
#include <cuda_runtime.h>
#include <cuda_bf16.h>
#include <math.h>

// Problem constants (fixed shapes)
#define B_    2
#define N_    2048
#define DIM_  2048
#define H_    16
#define HD_   128
#define INNER (H_*HD_)      // 2048
#define QKV_E (3*INNER)     // 6144
#define EPS_  1e-5f

// ---------------------------------------------------------------------------
// Scratch (no cudaMalloc -> __device__ globals)
// ---------------------------------------------------------------------------
__device__ float g_qkv[(size_t)B_*N_*QKV_E];   // [b*N+n][e]
__device__ float g_q  [(size_t)B_*H_*N_*HD_];  // [b][h][n][d]
__device__ float g_k  [(size_t)B_*H_*N_*HD_];
__device__ float g_att[(size_t)B_*N_*INNER];   // [b][n][h*HD+d]

// ---------------------------------------------------------------------------
// bf16 split helpers:  x = hi + lo  (hi,lo bf16; lo captures next 8 bits)
// ---------------------------------------------------------------------------
__device__ __forceinline__ void split2(float x0, float x1, unsigned &hi, unsigned &lo) {
    __nv_bfloat16 h0 = __float2bfloat16(x0);
    __nv_bfloat16 h1 = __float2bfloat16(x1);
    __nv_bfloat16 l0 = __float2bfloat16(x0 - __bfloat162float(h0));
    __nv_bfloat16 l1 = __float2bfloat16(x1 - __bfloat162float(h1));
    hi = (unsigned)__bfloat16_as_ushort(h0) | ((unsigned)__bfloat16_as_ushort(h1) << 16);
    lo = (unsigned)__bfloat16_as_ushort(l0) | ((unsigned)__bfloat16_as_ushort(l1) << 16);
}
__device__ __forceinline__ void split1(float x, __nv_bfloat16 &h, __nv_bfloat16 &l) {
    h = __float2bfloat16(x);
    l = __float2bfloat16(x - __bfloat162float(h));
}

// D(16x8) += A(16x16,row) * B(16x8,col)   bf16 in, f32 accum
__device__ __forceinline__ void mma16(float* c, const unsigned* a, const unsigned* b) {
    asm volatile(
        "mma.sync.aligned.m16n8k16.row.col.f32.bf16.bf16.f32 "
        "{%0,%1,%2,%3}, {%4,%5,%6,%7}, {%8,%9}, {%0,%1,%2,%3};\n"
        : "+f"(c[0]), "+f"(c[1]), "+f"(c[2]), "+f"(c[3])
        : "r"(a[0]), "r"(a[1]), "r"(a[2]), "r"(a[3]), "r"(b[0]), "r"(b[1]));
}

// ---------------------------------------------------------------------------
// bf16x3 GEMM (NT): C[M][Nc] = A[M][K] * Bw[Nc][K]^T.  Both K-contiguous.
// BM=BN=128, BK=32 (16 packed words), 256 threads (8 warps, warp tile 32x64).
// ---------------------------------------------------------------------------
#define GS 20   // smem word stride per row (16 data + 4 pad): conflict-free frags
__global__ __launch_bounds__(256)
void gemm_b3(const float* __restrict__ A, const float* __restrict__ Bw,
             float* __restrict__ C, int M, int Nc, int K)
{
    __shared__ unsigned Ah[128 * GS], Al[128 * GS];
    __shared__ unsigned Bh[128 * GS], Bl[128 * GS];

    const int tid  = threadIdx.x;
    const int lane = tid & 31;
    const int grp  = lane >> 2;     // 0..7
    const int tig  = lane & 3;      // 0..3
    const int w    = tid >> 5;
    const int wM   = (w & 3) * 32;
    const int wN   = (w >> 2) * 64;
    const int bm   = blockIdx.y * 128;
    const int bn   = blockIdx.x * 128;

    const int lr  = tid >> 3;        // 0..31 row within 32-row group
    const int lcw = (tid & 7) * 2;   // word col 0..14 (float col = 2*lcw)

    float acc[2][8][4] = {};
    float4 pa[4], pb[4];

    const float* Ab = A  + (size_t)bm * K;
    const float* Bb = Bw + (size_t)bn * K;

    // preload tile 0
#pragma unroll
    for (int it = 0; it < 4; it++) {
        pa[it] = *(const float4*)(Ab + (size_t)(lr + it * 32) * K + lcw * 2);
        pb[it] = *(const float4*)(Bb + (size_t)(lr + it * 32) * K + lcw * 2);
    }
#pragma unroll
    for (int it = 0; it < 4; it++) {
        const int ro = (lr + it * 32) * GS + lcw;
        split2(pa[it].x, pa[it].y, Ah[ro],     Al[ro]);
        split2(pa[it].z, pa[it].w, Ah[ro + 1], Al[ro + 1]);
        split2(pb[it].x, pb[it].y, Bh[ro],     Bl[ro]);
        split2(pb[it].z, pb[it].w, Bh[ro + 1], Bl[ro + 1]);
    }
    __syncthreads();

    for (int k0 = 0; k0 < K; k0 += 32) {
        const bool more = (k0 + 32) < K;
        if (more) {
#pragma unroll
            for (int it = 0; it < 4; it++) {
                pa[it] = *(const float4*)(Ab + (size_t)(lr + it * 32) * K + k0 + 32 + lcw * 2);
                pb[it] = *(const float4*)(Bb + (size_t)(lr + it * 32) * K + k0 + 32 + lcw * 2);
            }
        }
#pragma unroll
        for (int kk = 0; kk < 2; kk++) {       // two k16 chunks
            unsigned afh[2][4], afl[2][4], bfh[8][2], bfl[8][2];
#pragma unroll
            for (int mt = 0; mt < 2; mt++) {
                const int r = wM + mt * 16 + grp;
                const int i0 =  r      * GS + kk * 8 + tig;
                const int i1 = (r + 8) * GS + kk * 8 + tig;
                afh[mt][0] = Ah[i0];     afh[mt][1] = Ah[i1];
                afh[mt][2] = Ah[i0 + 4]; afh[mt][3] = Ah[i1 + 4];
                afl[mt][0] = Al[i0];     afl[mt][1] = Al[i1];
                afl[mt][2] = Al[i0 + 4]; afl[mt][3] = Al[i1 + 4];
            }
#pragma unroll
            for (int nt = 0; nt < 8; nt++) {
                const int n = wN + nt * 8 + grp;
                const int i0 = n * GS + kk * 8 + tig;
                bfh[nt][0] = Bh[i0]; bfh[nt][1] = Bh[i0 + 4];
                bfl[nt][0] = Bl[i0]; bfl[nt][1] = Bl[i0 + 4];
            }
#pragma unroll
            for (int mt = 0; mt < 2; mt++)
#pragma unroll
                for (int nt = 0; nt < 8; nt++) {
                    mma16(acc[mt][nt], afh[mt], bfh[nt]);
                    mma16(acc[mt][nt], afh[mt], bfl[nt]);
                    mma16(acc[mt][nt], afl[mt], bfh[nt]);
                }
        }
        __syncthreads();
        if (more) {
#pragma unroll
            for (int it = 0; it < 4; it++) {
                const int ro = (lr + it * 32) * GS + lcw;
                split2(pa[it].x, pa[it].y, Ah[ro],     Al[ro]);
                split2(pa[it].z, pa[it].w, Ah[ro + 1], Al[ro + 1]);
                split2(pb[it].x, pb[it].y, Bh[ro],     Bl[ro]);
                split2(pb[it].z, pb[it].w, Bh[ro + 1], Bl[ro + 1]);
            }
            __syncthreads();
        }
    }

#pragma unroll
    for (int mt = 0; mt < 2; mt++)
#pragma unroll
        for (int nt = 0; nt < 8; nt++) {
            const int r = bm + wM + mt * 16 + grp;
            const int c = bn + wN + nt * 8 + 2 * tig;
            *(float2*)(C + (size_t)r       * Nc + c) = make_float2(acc[mt][nt][0], acc[mt][nt][1]);
            *(float2*)(C + (size_t)(r + 8) * Nc + c) = make_float2(acc[mt][nt][2], acc[mt][nt][3]);
        }
}

// ---------------------------------------------------------------------------
// RMSNorm + RoPE + relayout for Q,K. grid (N,H,B), block 128.
// ---------------------------------------------------------------------------
__global__ __launch_bounds__(128)
void qk_norm_rope(const float* __restrict__ qkv,
                  const float* __restrict__ qg, const float* __restrict__ kg,
                  const float* __restrict__ freqs,
                  float* __restrict__ Qo, float* __restrict__ Ko)
{
    const int n = blockIdx.x, h = blockIdx.y, b = blockIdx.z;
    const int d = threadIdx.x;

    const float* base = qkv + (size_t)(b * N_ + n) * QKV_E + h * HD_ + d;
    float qv = base[0];
    float kv = base[INNER];

    __shared__ float red[2][4];
    float sq = qv * qv, sk = kv * kv;
#pragma unroll
    for (int off = 16; off; off >>= 1) {
        sq += __shfl_xor_sync(0xffffffffu, sq, off);
        sk += __shfl_xor_sync(0xffffffffu, sk, off);
    }
    const int warp = d >> 5, lane = d & 31;
    if (lane == 0) { red[0][warp] = sq; red[1][warp] = sk; }
    __syncthreads();
    sq = red[0][0] + red[0][1] + red[0][2] + red[0][3];
    sk = red[1][0] + red[1][1] + red[1][2] + red[1][3];

    const float rq = rsqrtf(sq * (1.0f / HD_) + EPS_);
    const float rk = rsqrtf(sk * (1.0f / HD_) + EPS_);
    qv = qv * rq * qg[d];
    kv = kv * rk * kg[d];

    const float* f = freqs + ((size_t)(b * N_ + n) * (HD_ / 2) + (d >> 1)) * 2;
    const float c = f[0], s = f[1];
    const float qp = __shfl_xor_sync(0xffffffffu, qv, 1);
    const float kp = __shfl_xor_sync(0xffffffffu, kv, 1);
    float qo, ko;
    if ((d & 1) == 0) { qo = qv * c - qp * s;  ko = kv * c - kp * s; }
    else              { qo = qp * s + qv * c;  ko = kp * s + kv * c; }

    const size_t oidx = (((size_t)(b * H_ + h) * N_ + n) * HD_ + d);
    Qo[oidx] = qo;
    Ko[oidx] = ko;
}

// ---------------------------------------------------------------------------
// Flash attention on tensor cores, bf16x3.
// CTA: 256 threads (8 warps). BQ=128 (16 rows/warp), KV tile = 64.
// Q hi/lo in registers; K hi/lo, V hi/lo (key-pair packed), P hi/lo in smem.
// grid (N/128, H, B).
// ---------------------------------------------------------------------------
#define KSTR 68    // K smem word stride per key row (64 data + 4 pad)
#define VSTR 132   // V smem word stride per key-pair row (128 d + 4 pad)
#define PSTR 36    // P smem word stride per q row (32 data + 4 pad)
#define FLASH_SMEM_WORDS (2*64*KSTR + 2*32*VSTR + 2*8*16*PSTR)
#define FLASH_SMEM_BYTES (FLASH_SMEM_WORDS * 4)

__global__ __launch_bounds__(256)
void flash_b3(const float* __restrict__ Q, const float* __restrict__ K,
              const float* __restrict__ qkv, float* __restrict__ Oo)
{
    extern __shared__ unsigned sm[];
    unsigned* Kh = sm;
    unsigned* Kl = Kh + 64 * KSTR;
    unsigned* Vh = Kl + 64 * KSTR;             // [32 keypair][VSTR]
    unsigned* Vl = Vh + 32 * VSTR;
    unsigned* Ph = Vl + 32 * VSTR;             // [8 warps][16][PSTR]
    unsigned* Pl = Ph + 8 * 16 * PSTR;

    const int tid  = threadIdx.x;
    const int lane = tid & 31;
    const int w    = tid >> 5;
    const int grp  = lane >> 2;
    const int tig  = lane & 3;
    const int qt   = blockIdx.x, h = blockIdx.y, b = blockIdx.z;
    const size_t bh = ((size_t)b * H_ + h) * (size_t)N_ * HD_;
    const int qrow0 = qt * 128 + w * 16;

    // Q fragments hi/lo (scale folded in before split): 8 k16 chunks over HD
    const float scale = 0.08838834764831845f;  // 1/sqrt(128)
    unsigned aqh[8][4], aql[8][4];
    const float* Qb = Q + bh + (size_t)qrow0 * HD_;
#pragma unroll
    for (int kk = 0; kk < 8; kk++) {
        const int c0 = kk * 16 + 2 * tig;
        float2 x0 = *(const float2*)(Qb + (size_t) grp      * HD_ + c0);
        float2 x1 = *(const float2*)(Qb + (size_t)(grp + 8) * HD_ + c0);
        float2 x2 = *(const float2*)(Qb + (size_t) grp      * HD_ + c0 + 8);
        float2 x3 = *(const float2*)(Qb + (size_t)(grp + 8) * HD_ + c0 + 8);
        split2(x0.x * scale, x0.y * scale, aqh[kk][0], aql[kk][0]);
        split2(x1.x * scale, x1.y * scale, aqh[kk][1], aql[kk][1]);
        split2(x2.x * scale, x2.y * scale, aqh[kk][2], aql[kk][2]);
        split2(x3.x * scale, x3.y * scale, aqh[kk][3], aql[kk][3]);
    }

    float o[16][4] = {};
    float m[2] = { -INFINITY, -INFINITY };
    float l[2] = { 0.f, 0.f };
    unsigned* Pwh = Ph + w * 16 * PSTR;
    unsigned* Pwl = Pl + w * 16 * PSTR;

    const float* Kb = K + bh;
    const float* Vb = qkv + (size_t)b * N_ * QKV_E + 2 * INNER + h * HD_; // row stride QKV_E

    const int ldr = tid >> 5;         // 0..7 (key row)
    const int ldc = (tid & 31) * 4;   // float col 0..124

    __nv_bfloat16* vhb = (__nv_bfloat16*)Vh;
    __nv_bfloat16* vlb = (__nv_bfloat16*)Vl;

    for (int kt = 0; kt < N_ / 64; kt++) {
        const float* Kt = Kb + (size_t)kt * 64 * HD_;
        const float* Vt = Vb + (size_t)kt * 64 * QKV_E;
#pragma unroll
        for (int it = 0; it < 8; it++) {
            const int r = ldr + it * 8;
            float4 k4 = *(const float4*)(Kt + (size_t)r * HD_   + ldc);
            float4 v4 = *(const float4*)(Vt + (size_t)r * QKV_E + ldc);
            const int kro = r * KSTR + ldc / 2;
            split2(k4.x, k4.y, Kh[kro],     Kl[kro]);
            split2(k4.z, k4.w, Kh[kro + 1], Kl[kro + 1]);
            // V transposed pack: bf16 index ((r>>1)*VSTR + d)*2 + (r&1)
            const int vb0 = ((r >> 1) * VSTR + ldc) * 2 + (r & 1);
            float vv[4] = { v4.x, v4.y, v4.z, v4.w };
#pragma unroll
            for (int j = 0; j < 4; j++) {
                __nv_bfloat16 hh, ll;
                split1(vv[j], hh, ll);
                vhb[vb0 + 2 * j] = hh;
                vlb[vb0 + 2 * j] = ll;
            }
        }
        __syncthreads();

        // ---- S = Q K^T : warp computes 16 x 64 ----
        float s[8][4] = {};
#pragma unroll
        for (int kk = 0; kk < 8; kk++) {
#pragma unroll
            for (int nt = 0; nt < 8; nt++) {
                const int n = nt * 8 + grp;
                const int i0 = n * KSTR + kk * 8 + tig;
                unsigned bkh[2], bkl[2];
                bkh[0] = Kh[i0]; bkh[1] = Kh[i0 + 4];
                bkl[0] = Kl[i0]; bkl[1] = Kl[i0 + 4];
                mma16(s[nt], aqh[kk], bkh);
                mma16(s[nt], aqh[kk], bkl);
                mma16(s[nt], aql[kk], bkh);
            }
        }

        // ---- online softmax on fragments (rows grp, grp+8) ----
#pragma unroll
        for (int i = 0; i < 2; i++) {
            float rm = -INFINITY;
#pragma unroll
            for (int nt = 0; nt < 8; nt++)
                rm = fmaxf(rm, fmaxf(s[nt][2 * i], s[nt][2 * i + 1]));
            rm = fmaxf(rm, __shfl_xor_sync(0xffffffffu, rm, 1));
            rm = fmaxf(rm, __shfl_xor_sync(0xffffffffu, rm, 2));
            const float mn    = fmaxf(m[i], rm);
            const float alpha = __expf(m[i] - mn);
            m[i] = mn;
            float rs = 0.f;
#pragma unroll
            for (int nt = 0; nt < 8; nt++) {
                const float p0 = __expf(s[nt][2 * i]     - mn);
                const float p1 = __expf(s[nt][2 * i + 1] - mn);
                rs += p0 + p1;
                const int off = (grp + 8 * i) * PSTR + nt * 4 + tig;
                split2(p0, p1, Pwh[off], Pwl[off]);
            }
            rs += __shfl_xor_sync(0xffffffffu, rs, 1);
            rs += __shfl_xor_sync(0xffffffffu, rs, 2);
            l[i] = l[i] * alpha + rs;
#pragma unroll
            for (int nt = 0; nt < 16; nt++) {
                o[nt][2 * i]     *= alpha;
                o[nt][2 * i + 1] *= alpha;
            }
        }
        __syncwarp();

        // ---- O += P V : warp computes 16 x 128 (4 k16 chunks over keys) ----
#pragma unroll
        for (int kk = 0; kk < 4; kk++) {
            unsigned aph[4], apl[4];
            const int i0 =  grp      * PSTR + kk * 8 + tig;
            const int i1 = (grp + 8) * PSTR + kk * 8 + tig;
            aph[0] = Pwh[i0]; aph[1] = Pwh[i1]; aph[2] = Pwh[i0 + 4]; aph[3] = Pwh[i1 + 4];
            apl[0] = Pwl[i0]; apl[1] = Pwl[i1]; apl[2] = Pwl[i0 + 4]; apl[3] = Pwl[i1 + 4];
#pragma unroll
            for (int nt = 0; nt < 16; nt++) {
                const int d = nt * 8 + grp;
                const int j0 = (kk * 8 + tig)     * VSTR + d;
                const int j1 = (kk * 8 + tig + 4) * VSTR + d;
                unsigned bvh[2], bvl[2];
                bvh[0] = Vh[j0]; bvh[1] = Vh[j1];
                bvl[0] = Vl[j0]; bvl[1] = Vl[j1];
                mma16(o[nt], aph, bvh);
                mma16(o[nt], aph, bvl);
                mma16(o[nt], apl, bvh);
            }
        }
        __syncthreads();
    }

    // ---- epilogue ----
#pragma unroll
    for (int i = 0; i < 2; i++) {
        const float inv = 1.0f / l[i];
        const int n = qrow0 + grp + 8 * i;
        float* dst = Oo + ((size_t)b * N_ + n) * INNER + h * HD_;
#pragma unroll
        for (int nt = 0; nt < 16; nt++)
            *(float2*)(dst + nt * 8 + 2 * tig) =
                make_float2(o[nt][2 * i] * inv, o[nt][2 * i + 1] * inv);
    }
}

// ---------------------------------------------------------------------------
// Launch
// ---------------------------------------------------------------------------
extern "C" void kernel_launch(void* const* d_in, const int* in_sizes, int n_in,
                              void* d_out, int out_size)
{
    const float* x     = (const float*)d_in[0];   // [2,2048,2048]
    const float* Wqkv  = (const float*)d_in[1];   // [6144,2048]
    const float* qg    = (const float*)d_in[2];   // [128]
    const float* kg    = (const float*)d_in[3];   // [128]
    const float* Wout  = (const float*)d_in[4];   // [2048,2048]
    const float* freqs = (const float*)d_in[5];   // [2,2048,64,2]
    float* out = (float*)d_out;                   // [2,2048,2048]

    void *p_qkv, *p_q, *p_k, *p_att;
    cudaGetSymbolAddress(&p_qkv, g_qkv);
    cudaGetSymbolAddress(&p_q,   g_q);
    cudaGetSymbolAddress(&p_k,   g_k);
    cudaGetSymbolAddress(&p_att, g_att);
    float* qkv = (float*)p_qkv;
    float* q   = (float*)p_q;
    float* k   = (float*)p_k;
    float* att = (float*)p_att;

    cudaFuncSetAttribute(flash_b3, cudaFuncAttributeMaxDynamicSharedMemorySize,
                         FLASH_SMEM_BYTES);

    // 1) QKV projection: [4096,2048] x [6144,2048]^T -> [4096,6144]
    gemm_b3<<<dim3(QKV_E / 128, (B_ * N_) / 128), 256>>>(
        x, Wqkv, qkv, B_ * N_, QKV_E, DIM_);

    // 2) RMSNorm + RoPE + relayout (Q,K only; V read from qkv directly)
    qk_norm_rope<<<dim3(N_, H_, B_), 128>>>(qkv, qg, kg, freqs, q, k);

    // 3) attention
    flash_b3<<<dim3(N_ / 128, H_, B_), 256, FLASH_SMEM_BYTES>>>(q, k, qkv, att);

    // 4) output projection: [4096,2048] x [2048,2048]^T -> [4096,2048]
    gemm_b3<<<dim3(DIM_ / 128, (B_ * N_) / 128), 256>>>(
        att, Wout, out, B_ * N_, DIM_, INNER);
}

// round 6
// speedup vs baseline: 3.2058x; 1.1212x over previous
#include <cuda_runtime.h>
#include <cuda_bf16.h>
#include <math.h>

// Problem constants (fixed shapes)
#define B_    2
#define N_    2048
#define DIM_  2048
#define H_    16
#define HD_   128
#define INNER (H_*HD_)      // 2048
#define QKV_E (3*INNER)     // 6144
#define EPS_  1e-5f

// ---------------------------------------------------------------------------
// Scratch (no cudaMalloc -> __device__ globals)
// ---------------------------------------------------------------------------
__device__ float g_qkv[(size_t)B_*N_*QKV_E];            // [b*N+n][e]
__device__ float g_q  [(size_t)B_*H_*N_*HD_];           // [b][h][n][d] fp32
__device__ __nv_bfloat16 g_kh[(size_t)B_*H_*N_*HD_];    // [b][h][n][d] bf16 hi
__device__ __nv_bfloat16 g_kl[(size_t)B_*H_*N_*HD_];    // lo
__device__ unsigned g_vh[(size_t)B_*H_*(N_/2)*HD_];     // [b][h][kp][d] packed pair hi
__device__ unsigned g_vl[(size_t)B_*H_*(N_/2)*HD_];     // lo
__device__ float g_att[(size_t)B_*N_*INNER];            // [b][n][h*HD+d]

// ---------------------------------------------------------------------------
// helpers
// ---------------------------------------------------------------------------
__device__ __forceinline__ void split2(float x0, float x1, unsigned &hi, unsigned &lo) {
    __nv_bfloat16 h0 = __float2bfloat16(x0);
    __nv_bfloat16 h1 = __float2bfloat16(x1);
    __nv_bfloat16 l0 = __float2bfloat16(x0 - __bfloat162float(h0));
    __nv_bfloat16 l1 = __float2bfloat16(x1 - __bfloat162float(h1));
    hi = (unsigned)__bfloat16_as_ushort(h0) | ((unsigned)__bfloat16_as_ushort(h1) << 16);
    lo = (unsigned)__bfloat16_as_ushort(l0) | ((unsigned)__bfloat16_as_ushort(l1) << 16);
}
__device__ __forceinline__ void split1(float x, __nv_bfloat16 &h, __nv_bfloat16 &l) {
    h = __float2bfloat16(x);
    l = __float2bfloat16(x - __bfloat162float(h));
}
__device__ __forceinline__ float ex2f(float x) {
    float y; asm("ex2.approx.f32 %0, %1;" : "=f"(y) : "f"(x)); return y;
}
// D(16x8) += A(16x16,row) * B(16x8,col)   bf16 in, f32 accum
__device__ __forceinline__ void mma16(float* c, const unsigned* a, const unsigned* b) {
    asm volatile(
        "mma.sync.aligned.m16n8k16.row.col.f32.bf16.bf16.f32 "
        "{%0,%1,%2,%3}, {%4,%5,%6,%7}, {%8,%9}, {%0,%1,%2,%3};\n"
        : "+f"(c[0]), "+f"(c[1]), "+f"(c[2]), "+f"(c[3])
        : "r"(a[0]), "r"(a[1]), "r"(a[2]), "r"(a[3]), "r"(b[0]), "r"(b[1]));
}
__device__ __forceinline__ void cp16(unsigned dst, const void* src) {
    asm volatile("cp.async.cg.shared.global [%0], [%1], 16;" :: "r"(dst), "l"(src));
}
__device__ __forceinline__ void cp_commit() {
    asm volatile("cp.async.commit_group;");
}

// ---------------------------------------------------------------------------
// bf16x3 GEMM (NT): C[M][Nc] = A[M][K] * Bw[Nc][K]^T.  (unchanged from R5)
// ---------------------------------------------------------------------------
#define GS 20
__global__ __launch_bounds__(256)
void gemm_b3(const float* __restrict__ A, const float* __restrict__ Bw,
             float* __restrict__ C, int M, int Nc, int K)
{
    __shared__ unsigned Ah[128 * GS], Al[128 * GS];
    __shared__ unsigned Bh[128 * GS], Bl[128 * GS];

    const int tid  = threadIdx.x;
    const int lane = tid & 31;
    const int grp  = lane >> 2;
    const int tig  = lane & 3;
    const int w    = tid >> 5;
    const int wM   = (w & 3) * 32;
    const int wN   = (w >> 2) * 64;
    const int bm   = blockIdx.y * 128;
    const int bn   = blockIdx.x * 128;

    const int lr  = tid >> 3;
    const int lcw = (tid & 7) * 2;

    float acc[2][8][4] = {};
    float4 pa[4], pb[4];

    const float* Ab = A  + (size_t)bm * K;
    const float* Bb = Bw + (size_t)bn * K;

#pragma unroll
    for (int it = 0; it < 4; it++) {
        pa[it] = *(const float4*)(Ab + (size_t)(lr + it * 32) * K + lcw * 2);
        pb[it] = *(const float4*)(Bb + (size_t)(lr + it * 32) * K + lcw * 2);
    }
#pragma unroll
    for (int it = 0; it < 4; it++) {
        const int ro = (lr + it * 32) * GS + lcw;
        split2(pa[it].x, pa[it].y, Ah[ro],     Al[ro]);
        split2(pa[it].z, pa[it].w, Ah[ro + 1], Al[ro + 1]);
        split2(pb[it].x, pb[it].y, Bh[ro],     Bl[ro]);
        split2(pb[it].z, pb[it].w, Bh[ro + 1], Bl[ro + 1]);
    }
    __syncthreads();

    for (int k0 = 0; k0 < K; k0 += 32) {
        const bool more = (k0 + 32) < K;
        if (more) {
#pragma unroll
            for (int it = 0; it < 4; it++) {
                pa[it] = *(const float4*)(Ab + (size_t)(lr + it * 32) * K + k0 + 32 + lcw * 2);
                pb[it] = *(const float4*)(Bb + (size_t)(lr + it * 32) * K + k0 + 32 + lcw * 2);
            }
        }
#pragma unroll
        for (int kk = 0; kk < 2; kk++) {
            unsigned afh[2][4], afl[2][4], bfh[8][2], bfl[8][2];
#pragma unroll
            for (int mt = 0; mt < 2; mt++) {
                const int r = wM + mt * 16 + grp;
                const int i0 =  r      * GS + kk * 8 + tig;
                const int i1 = (r + 8) * GS + kk * 8 + tig;
                afh[mt][0] = Ah[i0];     afh[mt][1] = Ah[i1];
                afh[mt][2] = Ah[i0 + 4]; afh[mt][3] = Ah[i1 + 4];
                afl[mt][0] = Al[i0];     afl[mt][1] = Al[i1];
                afl[mt][2] = Al[i0 + 4]; afl[mt][3] = Al[i1 + 4];
            }
#pragma unroll
            for (int nt = 0; nt < 8; nt++) {
                const int n = wN + nt * 8 + grp;
                const int i0 = n * GS + kk * 8 + tig;
                bfh[nt][0] = Bh[i0]; bfh[nt][1] = Bh[i0 + 4];
                bfl[nt][0] = Bl[i0]; bfl[nt][1] = Bl[i0 + 4];
            }
#pragma unroll
            for (int mt = 0; mt < 2; mt++)
#pragma unroll
                for (int nt = 0; nt < 8; nt++) {
                    mma16(acc[mt][nt], afh[mt], bfh[nt]);
                    mma16(acc[mt][nt], afh[mt], bfl[nt]);
                    mma16(acc[mt][nt], afl[mt], bfh[nt]);
                }
        }
        __syncthreads();
        if (more) {
#pragma unroll
            for (int it = 0; it < 4; it++) {
                const int ro = (lr + it * 32) * GS + lcw;
                split2(pa[it].x, pa[it].y, Ah[ro],     Al[ro]);
                split2(pa[it].z, pa[it].w, Ah[ro + 1], Al[ro + 1]);
                split2(pb[it].x, pb[it].y, Bh[ro],     Bl[ro]);
                split2(pb[it].z, pb[it].w, Bh[ro + 1], Bl[ro + 1]);
            }
            __syncthreads();
        }
    }

#pragma unroll
    for (int mt = 0; mt < 2; mt++)
#pragma unroll
        for (int nt = 0; nt < 8; nt++) {
            const int r = bm + wM + mt * 16 + grp;
            const int c = bn + wN + nt * 8 + 2 * tig;
            *(float2*)(C + (size_t)r       * Nc + c) = make_float2(acc[mt][nt][0], acc[mt][nt][1]);
            *(float2*)(C + (size_t)(r + 8) * Nc + c) = make_float2(acc[mt][nt][2], acc[mt][nt][3]);
        }
}

// ---------------------------------------------------------------------------
// RMSNorm + RoPE + relayout. Q -> fp32, K -> split bf16 hi/lo.
// grid (N, H, B), block 128.
// ---------------------------------------------------------------------------
__global__ __launch_bounds__(128)
void qk_norm_rope(const float* __restrict__ qkv,
                  const float* __restrict__ qg, const float* __restrict__ kg,
                  const float* __restrict__ freqs,
                  float* __restrict__ Qo,
                  __nv_bfloat16* __restrict__ Kho, __nv_bfloat16* __restrict__ Klo)
{
    const int n = blockIdx.x, h = blockIdx.y, b = blockIdx.z;
    const int d = threadIdx.x;

    const float* base = qkv + (size_t)(b * N_ + n) * QKV_E + h * HD_ + d;
    float qv = base[0];
    float kv = base[INNER];

    __shared__ float red[2][4];
    float sq = qv * qv, sk = kv * kv;
#pragma unroll
    for (int off = 16; off; off >>= 1) {
        sq += __shfl_xor_sync(0xffffffffu, sq, off);
        sk += __shfl_xor_sync(0xffffffffu, sk, off);
    }
    const int warp = d >> 5, lane = d & 31;
    if (lane == 0) { red[0][warp] = sq; red[1][warp] = sk; }
    __syncthreads();
    sq = red[0][0] + red[0][1] + red[0][2] + red[0][3];
    sk = red[1][0] + red[1][1] + red[1][2] + red[1][3];

    const float rq = rsqrtf(sq * (1.0f / HD_) + EPS_);
    const float rk = rsqrtf(sk * (1.0f / HD_) + EPS_);
    qv = qv * rq * qg[d];
    kv = kv * rk * kg[d];

    const float* f = freqs + ((size_t)(b * N_ + n) * (HD_ / 2) + (d >> 1)) * 2;
    const float c = f[0], s = f[1];
    const float qp = __shfl_xor_sync(0xffffffffu, qv, 1);
    const float kp = __shfl_xor_sync(0xffffffffu, kv, 1);
    float qo, ko;
    if ((d & 1) == 0) { qo = qv * c - qp * s;  ko = kv * c - kp * s; }
    else              { qo = qp * s + qv * c;  ko = kp * s + kv * c; }

    const size_t oidx = (((size_t)(b * H_ + h) * N_ + n) * HD_ + d);
    Qo[oidx] = qo;
    __nv_bfloat16 hh, ll;
    split1(ko, hh, ll);
    Kho[oidx] = hh;
    Klo[oidx] = ll;
}

// ---------------------------------------------------------------------------
// V convert: fp32 strided [b][n][2*INNER + h*HD + d] -> key-pair-packed bf16
// words [b][h][kp][d] (low half = key 2kp, high half = key 2kp+1), hi/lo split.
// grid (N/64, H, B), block 256.
// ---------------------------------------------------------------------------
__global__ __launch_bounds__(256)
void v_convert(const float* __restrict__ qkv,
               unsigned* __restrict__ Vh, unsigned* __restrict__ Vl)
{
    const int t = blockIdx.x, h = blockIdx.y, b = blockIdx.z;
    const int tid = threadIdx.x;
    const int c = (tid & 31) * 4;
    const size_t obase = ((size_t)(b * H_ + h) * (N_ / 2) + t * 32) * HD_;

#pragma unroll
    for (int it = 0; it < 4; it++) {
        const int kp = (tid >> 5) + it * 8;   // 0..31 local pair row
        const int n0 = t * 64 + 2 * kp;
        const float* r0 = qkv + (size_t)(b * N_ + n0)     * QKV_E + 2 * INNER + h * HD_ + c;
        const float* r1 = qkv + (size_t)(b * N_ + n0 + 1) * QKV_E + 2 * INNER + h * HD_ + c;
        float4 a = *(const float4*)r0;
        float4 e = *(const float4*)r1;
        unsigned hw[4], lw[4];
        const float av[4] = { a.x, a.y, a.z, a.w };
        const float ev[4] = { e.x, e.y, e.z, e.w };
#pragma unroll
        for (int j = 0; j < 4; j++) {
            __nv_bfloat16 ah, al, eh, el;
            split1(av[j], ah, al);
            split1(ev[j], eh, el);
            hw[j] = (unsigned)__bfloat16_as_ushort(ah) | ((unsigned)__bfloat16_as_ushort(eh) << 16);
            lw[j] = (unsigned)__bfloat16_as_ushort(al) | ((unsigned)__bfloat16_as_ushort(el) << 16);
        }
        *(uint4*)(Vh + obase + (size_t)kp * HD_ + c) = make_uint4(hw[0], hw[1], hw[2], hw[3]);
        *(uint4*)(Vl + obase + (size_t)kp * HD_ + c) = make_uint4(lw[0], lw[1], lw[2], lw[3]);
    }
}

// ---------------------------------------------------------------------------
// Flash attention, bf16x3, cp.async double-buffered, P-in-registers.
// CTA: 256 threads (8 warps). BQ=128 (16 rows/warp), KV tile = 64 keys.
// grid (N/128, H, B).
// smem per stage (words): Kh 64*68, Kl 64*68, Vh 32*132, Vl 32*132
// ---------------------------------------------------------------------------
#define KSTR 68
#define VSTR 132
#define KH_OFF 0
#define KL_OFF (64*KSTR)
#define VH_OFF (2*64*KSTR)
#define VL_OFF (2*64*KSTR + 32*VSTR)
#define ST_WORDS (2*64*KSTR + 2*32*VSTR)   // 17152
#define FLASH_SMEM_BYTES (2 * ST_WORDS * 4)  // 137216

__global__ __launch_bounds__(256)
void flash3(const float* __restrict__ Q,
            const __nv_bfloat16* __restrict__ KhG, const __nv_bfloat16* __restrict__ KlG,
            const unsigned* __restrict__ VhG, const unsigned* __restrict__ VlG,
            float* __restrict__ Oo)
{
    extern __shared__ unsigned sm[];
    const unsigned smem_base = (unsigned)__cvta_generic_to_shared(sm);

    const int tid  = threadIdx.x;
    const int lane = tid & 31;
    const int w    = tid >> 5;
    const int grp  = lane >> 2;
    const int tig  = lane & 3;
    const int qt   = blockIdx.x, h = blockIdx.y, b = blockIdx.z;
    const size_t bh = (size_t)b * H_ + h;
    const int qrow0 = qt * 128 + w * 16;

    const __nv_bfloat16* KhB = KhG + bh * (size_t)N_ * HD_;
    const __nv_bfloat16* KlB = KlG + bh * (size_t)N_ * HD_;
    const unsigned*      VhB = VhG + bh * (size_t)(N_ / 2) * HD_;
    const unsigned*      VlB = VlG + bh * (size_t)(N_ / 2) * HD_;

    // ---- issue one KV tile via cp.async ----
    auto issue_tile = [&](int kt, int st) {
        const unsigned sbase = smem_base + (unsigned)(st * ST_WORDS) * 4u;
#pragma unroll
        for (int q2 = tid; q2 < 1024; q2 += 256) {
            const int n = q2 >> 4, ch = q2 & 15;
            const unsigned dof = (unsigned)(n * KSTR + ch * 4) * 4u;
            const char* sh = (const char*)(KhB + (size_t)(kt * 64 + n) * HD_) + ch * 16;
            const char* sl = (const char*)(KlB + (size_t)(kt * 64 + n) * HD_) + ch * 16;
            cp16(sbase + KH_OFF * 4u + dof, sh);
            cp16(sbase + KL_OFF * 4u + dof, sl);
        }
#pragma unroll
        for (int q2 = tid; q2 < 1024; q2 += 256) {
            const int kp = q2 >> 5, ch = q2 & 31;
            const unsigned dof = (unsigned)(kp * VSTR + ch * 4) * 4u;
            const char* sh = (const char*)(VhB + (size_t)(kt * 32 + kp) * HD_) + ch * 16;
            const char* sl = (const char*)(VlB + (size_t)(kt * 32 + kp) * HD_) + ch * 16;
            cp16(sbase + VH_OFF * 4u + dof, sh);
            cp16(sbase + VL_OFF * 4u + dof, sl);
        }
        cp_commit();
    };

    issue_tile(0, 0);

    // ---- Q fragments hi/lo (scale * log2e folded in) ----
    const float scale2 = 0.08838834764831845f * 1.4426950408889634f;
    unsigned aqh[8][4], aql[8][4];
    const float* Qb = Q + bh * (size_t)N_ * HD_ + (size_t)qrow0 * HD_;
#pragma unroll
    for (int kk = 0; kk < 8; kk++) {
        const int c0 = kk * 16 + 2 * tig;
        float2 x0 = *(const float2*)(Qb + (size_t) grp      * HD_ + c0);
        float2 x1 = *(const float2*)(Qb + (size_t)(grp + 8) * HD_ + c0);
        float2 x2 = *(const float2*)(Qb + (size_t) grp      * HD_ + c0 + 8);
        float2 x3 = *(const float2*)(Qb + (size_t)(grp + 8) * HD_ + c0 + 8);
        split2(x0.x * scale2, x0.y * scale2, aqh[kk][0], aql[kk][0]);
        split2(x1.x * scale2, x1.y * scale2, aqh[kk][1], aql[kk][1]);
        split2(x2.x * scale2, x2.y * scale2, aqh[kk][2], aql[kk][2]);
        split2(x3.x * scale2, x3.y * scale2, aqh[kk][3], aql[kk][3]);
    }

    float o[16][4] = {};
    float m[2] = { -INFINITY, -INFINITY };
    float l[2] = { 0.f, 0.f };

    for (int kt = 0; kt < N_ / 64; kt++) {
        const int st = kt & 1;
        if (kt + 1 < N_ / 64) {
            issue_tile(kt + 1, st ^ 1);
            asm volatile("cp.async.wait_group 1;");
        } else {
            asm volatile("cp.async.wait_group 0;");
        }
        __syncthreads();

        const unsigned* KhS = sm + st * ST_WORDS + KH_OFF;
        const unsigned* KlS = sm + st * ST_WORDS + KL_OFF;
        const unsigned* VhS = sm + st * ST_WORDS + VH_OFF;
        const unsigned* VlS = sm + st * ST_WORDS + VL_OFF;

        // ---- S = Q K^T : warp computes 16 x 64 (log2-scaled) ----
        float s[8][4] = {};
#pragma unroll
        for (int kk = 0; kk < 8; kk++) {
#pragma unroll
            for (int nt = 0; nt < 8; nt++) {
                const int i0 = (nt * 8 + grp) * KSTR + kk * 8 + tig;
                unsigned bkh[2], bkl[2];
                bkh[0] = KhS[i0]; bkh[1] = KhS[i0 + 4];
                bkl[0] = KlS[i0]; bkl[1] = KlS[i0 + 4];
                mma16(s[nt], aqh[kk], bkh);
                mma16(s[nt], aqh[kk], bkl);
                mma16(s[nt], aql[kk], bkh);
            }
        }

        // ---- online softmax (base-2); p overwrites s ----
#pragma unroll
        for (int i = 0; i < 2; i++) {
            float rm = -INFINITY;
#pragma unroll
            for (int nt = 0; nt < 8; nt++)
                rm = fmaxf(rm, fmaxf(s[nt][2 * i], s[nt][2 * i + 1]));
            rm = fmaxf(rm, __shfl_xor_sync(0xffffffffu, rm, 1));
            rm = fmaxf(rm, __shfl_xor_sync(0xffffffffu, rm, 2));
            const float mn    = fmaxf(m[i], rm);
            const float alpha = ex2f(m[i] - mn);
            m[i] = mn;
            float rs = 0.f;
#pragma unroll
            for (int nt = 0; nt < 8; nt++) {
                const float p0 = ex2f(s[nt][2 * i]     - mn);
                const float p1 = ex2f(s[nt][2 * i + 1] - mn);
                rs += p0 + p1;
                s[nt][2 * i]     = p0;
                s[nt][2 * i + 1] = p1;
            }
            rs += __shfl_xor_sync(0xffffffffu, rs, 1);
            rs += __shfl_xor_sync(0xffffffffu, rs, 2);
            l[i] = l[i] * alpha + rs;
#pragma unroll
            for (int nt = 0; nt < 16; nt++) {
                o[nt][2 * i]     *= alpha;
                o[nt][2 * i + 1] *= alpha;
            }
        }

        // ---- O += P V : P built directly from S fragments ----
#pragma unroll
        for (int kk = 0; kk < 4; kk++) {
            unsigned aph[4], apl[4];
            split2(s[2 * kk][0],     s[2 * kk][1],     aph[0], apl[0]);
            split2(s[2 * kk][2],     s[2 * kk][3],     aph[1], apl[1]);
            split2(s[2 * kk + 1][0], s[2 * kk + 1][1], aph[2], apl[2]);
            split2(s[2 * kk + 1][2], s[2 * kk + 1][3], aph[3], apl[3]);
#pragma unroll
            for (int nt = 0; nt < 16; nt++) {
                const int d  = nt * 8 + grp;
                const int j0 = (kk * 8 + tig)     * VSTR + d;
                const int j1 = (kk * 8 + tig + 4) * VSTR + d;
                unsigned bvh[2], bvl[2];
                bvh[0] = VhS[j0]; bvh[1] = VhS[j1];
                bvl[0] = VlS[j0]; bvl[1] = VlS[j1];
                mma16(o[nt], aph, bvh);
                mma16(o[nt], aph, bvl);
                mma16(o[nt], apl, bvh);
            }
        }
        __syncthreads();
    }

    // ---- epilogue ----
#pragma unroll
    for (int i = 0; i < 2; i++) {
        const float inv = 1.0f / l[i];
        const int n = qrow0 + grp + 8 * i;
        float* dst = Oo + ((size_t)b * N_ + n) * INNER + h * HD_;
#pragma unroll
        for (int nt = 0; nt < 16; nt++)
            *(float2*)(dst + nt * 8 + 2 * tig) =
                make_float2(o[nt][2 * i] * inv, o[nt][2 * i + 1] * inv);
    }
}

// ---------------------------------------------------------------------------
// Launch
// ---------------------------------------------------------------------------
extern "C" void kernel_launch(void* const* d_in, const int* in_sizes, int n_in,
                              void* d_out, int out_size)
{
    const float* x     = (const float*)d_in[0];   // [2,2048,2048]
    const float* Wqkv  = (const float*)d_in[1];   // [6144,2048]
    const float* qg    = (const float*)d_in[2];   // [128]
    const float* kg    = (const float*)d_in[3];   // [128]
    const float* Wout  = (const float*)d_in[4];   // [2048,2048]
    const float* freqs = (const float*)d_in[5];   // [2,2048,64,2]
    float* out = (float*)d_out;                   // [2,2048,2048]

    void *p_qkv, *p_q, *p_kh, *p_kl, *p_vh, *p_vl, *p_att;
    cudaGetSymbolAddress(&p_qkv, g_qkv);
    cudaGetSymbolAddress(&p_q,   g_q);
    cudaGetSymbolAddress(&p_kh,  g_kh);
    cudaGetSymbolAddress(&p_kl,  g_kl);
    cudaGetSymbolAddress(&p_vh,  g_vh);
    cudaGetSymbolAddress(&p_vl,  g_vl);
    cudaGetSymbolAddress(&p_att, g_att);
    float* qkv = (float*)p_qkv;
    float* q   = (float*)p_q;
    __nv_bfloat16* kh = (__nv_bfloat16*)p_kh;
    __nv_bfloat16* kl = (__nv_bfloat16*)p_kl;
    unsigned* vh = (unsigned*)p_vh;
    unsigned* vl = (unsigned*)p_vl;
    float* att = (float*)p_att;

    cudaFuncSetAttribute(flash3, cudaFuncAttributeMaxDynamicSharedMemorySize,
                         FLASH_SMEM_BYTES);

    // 1) QKV projection
    gemm_b3<<<dim3(QKV_E / 128, (B_ * N_) / 128), 256>>>(
        x, Wqkv, qkv, B_ * N_, QKV_E, DIM_);

    // 2) RMSNorm + RoPE (Q fp32, K split bf16), V convert
    qk_norm_rope<<<dim3(N_, H_, B_), 128>>>(qkv, qg, kg, freqs, q, kh, kl);
    v_convert<<<dim3(N_ / 64, H_, B_), 256>>>(qkv, vh, vl);

    // 3) attention
    flash3<<<dim3(N_ / 128, H_, B_), 256, FLASH_SMEM_BYTES>>>(q, kh, kl, vh, vl, att);

    // 4) output projection
    gemm_b3<<<dim3(DIM_ / 128, (B_ * N_) / 128), 256>>>(
        att, Wout, out, B_ * N_, DIM_, INNER);
}